// round 5
// baseline (speedup 1.0000x reference)
#include <cuda_runtime.h>
#include <math.h>

#define NHID 1024
#define NOUT 50257
#define MAXLEN 24
#define GRID 592
#define NPREF_BLK 207                 // blocks 385..591
#define NTILE ((NOUT + 7) / 8)        // 6283
#define PREF_F4 (96u * 1024u * 1024u / 16u)   // up to 96MB of out_W

// -------- device scratch --------
__device__ float g_cat[2 * NHID];
__device__ float g_x[NHID];
__device__ float g_gi[3 * NHID];      // W_ih@x + b_ih
__device__ float g_gh[3 * NHID];      // W_hh@h0 + b_hh
__device__ float g_logits[NOUT];
__device__ float g_pm[GRID];
__device__ float g_ps[GRID];
__device__ unsigned g_bar[4];         // epoch barriers (never reset)
__device__ float g_sink;

__device__ __forceinline__ float wredsum(float v) {
    #pragma unroll
    for (int o = 16; o; o >>= 1) v += __shfl_xor_sync(0xffffffffu, v, o);
    return v;
}
__device__ __forceinline__ float wredmax(float v) {
    #pragma unroll
    for (int o = 16; o; o >>= 1) v = fmaxf(v, __shfl_xor_sync(0xffffffffu, v, o));
    return v;
}
__device__ __forceinline__ float sigm(float x) { return 1.f / (1.f + expf(-x)); }
__device__ __forceinline__ float dot4(float4 a, float4 b) {
    return a.x * b.x + a.y * b.y + a.z * b.z + a.w * b.w;
}

__device__ __forceinline__ void bar_arrive_wait(int id) {
    __syncthreads();
    if (threadIdx.x == 0) {
        __threadfence();
        unsigned old = atomicAdd(&g_bar[id], 1u);
        unsigned target = old - (old % GRID) + GRID;
        volatile unsigned* p = &g_bar[id];
        while (*p < target) { __nanosleep(64); }
        __threadfence();
    }
    __syncthreads();
}

__global__ void __launch_bounds__(256, 4)
mega(const int* __restrict__ inp,
     const float* __restrict__ hidden,
     const float* __restrict__ enc_outs,
     const float* __restrict__ emb_W,
     const float* __restrict__ attn_W,
     const float* __restrict__ attn_b,
     const float* __restrict__ comb_W,
     const float* __restrict__ comb_b,
     const float* __restrict__ W_ih,
     const float* __restrict__ W_hh,
     const float* __restrict__ b_ih,
     const float* __restrict__ b_hh,
     const float* __restrict__ out_W,
     const float* __restrict__ out_b,
     float* __restrict__ logp,
     float* __restrict__ hout,
     float* __restrict__ attnw_out) {
    __shared__ float sv[2 * NHID];     // phase-local vector buffer
    __shared__ float sred[512];
    __shared__ float sscore[32];
    __shared__ float sw[MAXLEN];
    __shared__ unsigned s_tgt;
    __shared__ int s_stop;

    const int t = threadIdx.x;         // 256
    const int b = blockIdx.x;
    const int warp = t >> 5, lane = t & 31;

    if (b >= 385) {
        // ============ PREFETCH PATH (blocks 385..591) ============
        __syncthreads();
        if (t == 0) {
            atomicAdd(&g_bar[0], 1u);
            atomicAdd(&g_bar[1], 1u);
            unsigned old = atomicAdd(&g_bar[2], 1u);
            s_tgt = old - (old % GRID) + GRID;
            s_stop = 0;
        }
        __syncthreads();
        unsigned tgt = s_tgt;
        {
            const float4* w4 = (const float4*)out_W;
            const unsigned stride = NPREF_BLK * 256u;
            float acc = 0.f;
            for (unsigned i = (unsigned)(b - 385) * 256u + t; i < PREF_F4;
                 i += stride * 4u) {
                #pragma unroll
                for (int j = 0; j < 4; j++) {
                    unsigned idx = i + (unsigned)j * stride;
                    if (idx < PREF_F4) {
                        float4 v = __ldcg(w4 + idx);
                        acc += v.x + v.y + v.z + v.w;
                    }
                }
                __syncthreads();
                if (t == 0 &&
                    *(volatile unsigned*)&g_bar[2] >= tgt) s_stop = 1;
                __syncthreads();
                if (s_stop) break;
            }
            if (acc == -1.2345678e35f) g_sink = acc;   // defeat DCE
        }
        if (t == 0) {
            volatile unsigned* p = &g_bar[2];
            while (*p < tgt) { __nanosleep(64); }
            __threadfence();
        }
        __syncthreads();
    } else {
        // ============ ACTIVE PATH (blocks 0..384) ============
        // -------- Window A --------
        if (b == 0) {
            // attention
            const float4* e4 = (const float4*)(emb_W + (size_t)inp[0] * NHID);
            float4 ev = e4[t];
            ((float4*)sv)[t] = ev;
            ((float4*)g_cat)[t] = ev;
            ((float4*)(sv + NHID))[t] = ((const float4*)hidden)[t];
            __syncthreads();

            for (int r = warp; r < MAXLEN; r += 8) {
                const float* w = attn_W + (size_t)r * (2 * NHID);
                float acc = 0.f;
                #pragma unroll
                for (int q = 0; q < 64; q++) {
                    int idx = lane + 32 * q;
                    acc += w[idx] * sv[idx];
                }
                acc = wredsum(acc);
                if (lane == 0) sscore[r] = acc + attn_b[r];
            }
            __syncthreads();

            if (warp == 0) {
                float v = (lane < MAXLEN) ? sscore[lane] : -INFINITY;
                float m = wredmax(v);
                float p = (lane < MAXLEN) ? expf(v - m) : 0.f;
                float s = wredsum(p);
                float wv = p / s;
                if (lane < MAXLEN) {
                    sw[lane] = wv;
                    attnw_out[lane] = wv;
                }
            }
            __syncthreads();

            #pragma unroll
            for (int j = 0; j < 4; j++) {
                int col = t + 256 * j;
                float acc = 0.f;
                #pragma unroll
                for (int m2 = 0; m2 < MAXLEN; m2++)
                    acc += sw[m2] * enc_outs[m2 * NHID + col];
                g_cat[NHID + col] = acc;
            }
        } else {
            // gh = W_hh @ h0 + b_hh : blocks 1..384, warp-per-row (3072 rows)
            ((float4*)sv)[t] = ((const float4*)hidden)[t];
            __syncthreads();
            int r = (b - 1) * 8 + warp;
            const float4* w = (const float4*)(W_hh + (size_t)r * NHID);
            const float4* h4 = (const float4*)sv;
            float acc = 0.f;
            #pragma unroll
            for (int q = 0; q < 8; q++) {
                int idx = lane + 32 * q;
                acc += dot4(__ldcs(w + idx), h4[idx]);
            }
            acc = wredsum(acc);
            if (lane == 0) g_gh[r] = acc + b_hh[r];
        }
        bar_arrive_wait(0);

        // -------- Window B: comb GEMV + relu (blocks 0..127) --------
        if (b < 128) {
            ((float4*)sv)[t] = ((const float4*)g_cat)[t];
            ((float4*)sv)[t + 256] = ((const float4*)g_cat)[t + 256];
            __syncthreads();
            int row = b * 8 + warp;
            const float4* w4 = (const float4*)(comb_W + (size_t)row * (2 * NHID));
            const float4* sc4 = (const float4*)sv;
            float acc = 0.f;
            #pragma unroll
            for (int k = 0; k < 16; k++) {
                int idx = lane + 32 * k;
                acc += dot4(__ldcs(w4 + idx), sc4[idx]);
            }
            acc = wredsum(acc);
            if (lane == 0) g_x[row] = fmaxf(acc + comb_b[row], 0.f);
        }
        bar_arrive_wait(1);

        // -------- Window C: gi = W_ih @ x + b_ih (blocks 0..383) --------
        if (b < 384) {
            ((float4*)sv)[t] = ((const float4*)g_x)[t];   // first 256 float4
            __syncthreads();
            int r = b * 8 + warp;
            const float4* w = (const float4*)(W_ih + (size_t)r * NHID);
            const float4* x4 = (const float4*)sv;
            float acc = 0.f;
            #pragma unroll
            for (int q = 0; q < 8; q++) {
                int idx = lane + 32 * q;
                acc += dot4(__ldcs(w + idx), x4[idx]);
            }
            acc = wredsum(acc);
            if (lane == 0) g_gi[r] = acc + b_ih[r];
        }
        bar_arrive_wait(2);
    }

    // ============ Phase D (all 592 blocks) ============
    // prologue: redundantly compute h into shared from gi/gh
    {
        #pragma unroll
        for (int j = 0; j < 4; j++) {
            int k = t + 256 * j;
            float r = sigm(g_gi[k] + g_gh[k]);
            float z = sigm(g_gi[k + NHID] + g_gh[k + NHID]);
            float n = tanhf(g_gi[k + 2 * NHID] + r * g_gh[k + 2 * NHID]);
            float h = (1.f - z) * n + z * hidden[k];
            sv[k] = h;
            if (b == 0) hout[k] = h;
        }
        __syncthreads();
    }

    // logits GEMV + per-block online softmax
    {
        const float4* sh4 = (const float4*)sv;
        float mloc = -INFINITY, sloc = 0.f;
        for (int tile = b; tile < NTILE; tile += GRID) {
            int row = tile * 8 + warp;
            if (row < NOUT) {
                const float4* w = (const float4*)(out_W + (size_t)row * NHID);
                float acc = 0.f;
                #pragma unroll
                for (int k = 0; k < 8; k++) {
                    int idx = lane + 32 * k;
                    acc += dot4(__ldcs(w + idx), sh4[idx]);
                }
                acc = wredsum(acc);
                if (lane == 0) {
                    float y = acc + out_b[row];
                    g_logits[row] = y;
                    if (y > mloc) { sloc = sloc * __expf(mloc - y) + 1.f; mloc = y; }
                    else          { sloc += __expf(y - mloc); }
                }
            }
        }
        sred[t] = mloc; sred[256 + t] = sloc;
        __syncthreads();
        for (int o = 128; o; o >>= 1) {
            if (t < o) {
                float m1 = sred[t], s1 = sred[256 + t];
                float m2 = sred[t + o], s2 = sred[256 + t + o];
                float M = fmaxf(m1, m2);
                float S = (s1 > 0.f ? s1 * __expf(m1 - M) : 0.f) +
                          (s2 > 0.f ? s2 * __expf(m2 - M) : 0.f);
                sred[t] = M; sred[256 + t] = S;
            }
            __syncthreads();
        }
        if (t == 0) { g_pm[b] = sred[0]; g_ps[b] = sred[256]; }
    }
    bar_arrive_wait(3);

    // ============ Final: redundant reduce + logp write ============
    {
        float m = -INFINITY, s = 0.f;
        for (int i = t; i < GRID; i += 256) {
            float mb = g_pm[i], sb = g_ps[i];
            if (mb > m) { s = s * __expf(m - mb) + sb; m = mb; }
            else        { s += sb * __expf(mb - m); }
        }
        sred[t] = m; sred[256 + t] = s;
        __syncthreads();
        for (int o = 128; o; o >>= 1) {
            if (t < o) {
                float m1 = sred[t], s1 = sred[256 + t];
                float m2 = sred[t + o], s2 = sred[256 + t + o];
                float M = fmaxf(m1, m2);
                float S = (s1 > 0.f ? s1 * __expf(m1 - M) : 0.f) +
                          (s2 > 0.f ? s2 * __expf(m2 - M) : 0.f);
                sred[t] = M; sred[256 + t] = S;
            }
            __syncthreads();
        }
        float C = sred[0] + logf(sred[256]);
        int i = b * 256 + t;
        if (i < NOUT) logp[i] = g_logits[i] - C;
    }
}

extern "C" void kernel_launch(void* const* d_in, const int* in_sizes, int n_in,
                              void* d_out, int out_size) {
    const int*   inp      = (const int*)  d_in[0];
    const float* hidden   = (const float*)d_in[1];
    const float* enc_outs = (const float*)d_in[3];
    const float* emb_W    = (const float*)d_in[4];
    const float* attn_W   = (const float*)d_in[5];
    const float* attn_b   = (const float*)d_in[6];
    const float* comb_W   = (const float*)d_in[7];
    const float* comb_b   = (const float*)d_in[8];
    const float* W_ih     = (const float*)d_in[9];
    const float* W_hh     = (const float*)d_in[10];
    const float* b_ih     = (const float*)d_in[11];
    const float* b_hh     = (const float*)d_in[12];
    const float* out_W    = (const float*)d_in[13];
    const float* out_b    = (const float*)d_in[14];

    float* out   = (float*)d_out;
    float* logp  = out;                 // [50257]
    float* hout  = out + NOUT;          // [1024]
    float* attnw = out + NOUT + NHID;   // [24]

    mega<<<GRID, 256>>>(inp, hidden, enc_outs, emb_W, attn_W, attn_b,
                        comb_W, comb_b, W_ih, W_hh, b_ih, b_hh,
                        out_W, out_b, logp, hout, attnw);
}

// round 6
// speedup vs baseline: 1.0383x; 1.0383x over previous
#include <cuda_runtime.h>
#include <math.h>

#define NHID 1024
#define NOUT 50257
#define MAXLEN 24
#define GRID 592
#define NTILE ((NOUT + 7) / 8)        // 6283

// -------- device scratch --------
__device__ float g_cat[2 * NHID];
__device__ float g_x[NHID];
__device__ float g_gi[3 * NHID];      // W_ih@x + b_ih
__device__ float g_gh[3 * NHID];      // W_hh@h0 + b_hh
__device__ float g_logits[NOUT];
__device__ float g_pm[GRID];
__device__ float g_ps[GRID];
__device__ unsigned g_bar[4];         // epoch barriers (never reset)

__device__ __forceinline__ float wredsum(float v) {
    #pragma unroll
    for (int o = 16; o; o >>= 1) v += __shfl_xor_sync(0xffffffffu, v, o);
    return v;
}
__device__ __forceinline__ float wredmax(float v) {
    #pragma unroll
    for (int o = 16; o; o >>= 1) v = fmaxf(v, __shfl_xor_sync(0xffffffffu, v, o));
    return v;
}
__device__ __forceinline__ float sigm(float x) { return 1.f / (1.f + expf(-x)); }
__device__ __forceinline__ float dot4(float4 a, float4 b) {
    return a.x * b.x + a.y * b.y + a.z * b.z + a.w * b.w;
}

// arrive only (no wait) — epoch math stays valid since every block arrives
// at every barrier exactly once per launch.
__device__ __forceinline__ void bar_arrive(int id) {
    __syncthreads();
    if (threadIdx.x == 0) {
        __threadfence();
        atomicAdd(&g_bar[id], 1u);
    }
    __syncthreads();
}
__device__ __forceinline__ void bar_arrive_wait(int id) {
    __syncthreads();
    if (threadIdx.x == 0) {
        __threadfence();
        unsigned old = atomicAdd(&g_bar[id], 1u);
        unsigned target = old - (old % GRID) + GRID;
        volatile unsigned* p = &g_bar[id];
        while (*p < target) { __nanosleep(32); }
        __threadfence();
    }
    __syncthreads();
}

__global__ void __launch_bounds__(256, 4)
mega(const int* __restrict__ inp,
     const float* __restrict__ hidden,
     const float* __restrict__ enc_outs,
     const float* __restrict__ emb_W,
     const float* __restrict__ attn_W,
     const float* __restrict__ attn_b,
     const float* __restrict__ comb_W,
     const float* __restrict__ comb_b,
     const float* __restrict__ W_ih,
     const float* __restrict__ W_hh,
     const float* __restrict__ b_ih,
     const float* __restrict__ b_hh,
     const float* __restrict__ out_W,
     const float* __restrict__ out_b,
     float* __restrict__ logp,
     float* __restrict__ hout,
     float* __restrict__ attnw_out) {
    __shared__ float sv[2 * NHID];
    __shared__ float sred[512];
    __shared__ float sscore[32];
    __shared__ float sw[MAXLEN];

    const int t = threadIdx.x;         // 256
    const int b = blockIdx.x;
    const int warp = t >> 5, lane = t & 31;
    float4* sv4 = (float4*)sv;

    // ================= Window A =================
    if (b == 0) {
        // --- attention (vectorized) ---
        const float4* e4 = (const float4*)(emb_W + (size_t)inp[0] * NHID);
        float4 ev = e4[t];
        sv4[t] = ev;
        ((float4*)g_cat)[t] = ev;
        sv4[256 + t] = ((const float4*)hidden)[t];
        __syncthreads();

        for (int r = warp; r < MAXLEN; r += 8) {
            const float4* w = (const float4*)(attn_W + (size_t)r * (2 * NHID));
            float acc = 0.f;
            #pragma unroll
            for (int q = 0; q < 16; q++) {
                int idx = lane + 32 * q;
                acc += dot4(w[idx], sv4[idx]);
            }
            acc = wredsum(acc);
            if (lane == 0) sscore[r] = acc + attn_b[r];
        }
        __syncthreads();

        if (warp == 0) {
            float v = (lane < MAXLEN) ? sscore[lane] : -INFINITY;
            float m = wredmax(v);
            float p = (lane < MAXLEN) ? expf(v - m) : 0.f;
            float s = wredsum(p);
            float wv = p / s;
            if (lane < MAXLEN) {
                sw[lane] = wv;
                attnw_out[lane] = wv;
            }
        }
        __syncthreads();

        // context: thread t owns float4 column-chunk t
        {
            const float4* enc4 = (const float4*)enc_outs;
            float4 acc = make_float4(0.f, 0.f, 0.f, 0.f);
            #pragma unroll
            for (int m2 = 0; m2 < MAXLEN; m2++) {
                float wv = sw[m2];
                float4 v = enc4[m2 * 256 + t];
                acc.x += wv * v.x; acc.y += wv * v.y;
                acc.z += wv * v.z; acc.w += wv * v.w;
            }
            ((float4*)g_cat)[256 + t] = acc;
        }
    } else {
        // --- gh = W_hh @ h0 + b_hh : one row per warp across blocks 1..591 ---
        sv4[t] = ((const float4*)hidden)[t];
        __syncthreads();
        int r = (b - 1) * 8 + warp;
        if (r < 3 * NHID) {
            const float4* w = (const float4*)(W_hh + (size_t)r * NHID);
            float acc = 0.f;
            #pragma unroll
            for (int q = 0; q < 8; q++) {
                int idx = lane + 32 * q;
                acc += dot4(__ldcs(w + idx), sv4[idx]);
            }
            acc = wredsum(acc);
            if (lane == 0) g_gh[r] = acc + b_hh[r];
        }
    }

    if (b < 128) {
        // needs g_cat (from block 0's attention)
        bar_arrive_wait(0);

        // ================= Window B: comb GEMV + relu =================
        sv4[t] = ((const float4*)g_cat)[t];
        sv4[256 + t] = ((const float4*)g_cat)[256 + t];
        __syncthreads();
        int row = b * 8 + warp;
        const float4* w4 = (const float4*)(comb_W + (size_t)row * (2 * NHID));
        float acc = 0.f;
        #pragma unroll
        for (int k = 0; k < 16; k++) {
            int idx = lane + 32 * k;
            acc += dot4(__ldcs(w4 + idx), sv4[idx]);
        }
        acc = wredsum(acc);
        if (lane == 0) g_x[row] = fmaxf(acc + comb_b[row], 0.f);

        bar_arrive_wait(1);
    } else if (b < 384) {
        bar_arrive(0);
        bar_arrive_wait(1);      // need full g_x
    } else {
        bar_arrive(0);
        bar_arrive(1);
    }

    // ================= Window C: gi = W_ih @ x + b_ih (blocks 0..383) =================
    if (b < 384) {
        sv4[t] = ((const float4*)g_x)[t];
        __syncthreads();
        int r = b * 8 + warp;
        const float4* w = (const float4*)(W_ih + (size_t)r * NHID);
        float acc = 0.f;
        #pragma unroll
        for (int q = 0; q < 8; q++) {
            int idx = lane + 32 * q;
            acc += dot4(__ldcs(w + idx), sv4[idx]);
        }
        acc = wredsum(acc);
        if (lane == 0) g_gi[r] = acc + b_ih[r];
    }
    bar_arrive_wait(2);

    // ================= Phase D prologue: redundant GRU gate math =================
    {
        #pragma unroll
        for (int j = 0; j < 4; j++) {
            int k = t + 256 * j;
            float r = sigm(g_gi[k] + g_gh[k]);
            float z = sigm(g_gi[k + NHID] + g_gh[k + NHID]);
            float n = tanhf(g_gi[k + 2 * NHID] + r * g_gh[k + 2 * NHID]);
            float h = (1.f - z) * n + z * hidden[k];
            sv[k] = h;
            if (b == 0) hout[k] = h;
        }
        __syncthreads();
    }

    // ================= Phase D: logits GEMV + per-block online softmax =================
    {
        float mloc = -INFINITY, sloc = 0.f;
        for (int tile = b; tile < NTILE; tile += GRID) {
            int row = tile * 8 + warp;
            if (row < NOUT) {
                const float4* w = (const float4*)(out_W + (size_t)row * NHID);
                float acc = 0.f;
                #pragma unroll
                for (int k = 0; k < 8; k++) {
                    int idx = lane + 32 * k;
                    acc += dot4(__ldcs(w + idx), sv4[idx]);
                }
                acc = wredsum(acc);
                if (lane == 0) {
                    float y = acc + out_b[row];
                    g_logits[row] = y;
                    if (y > mloc) { sloc = sloc * __expf(mloc - y) + 1.f; mloc = y; }
                    else          { sloc += __expf(y - mloc); }
                }
            }
        }
        sred[t] = mloc; sred[256 + t] = sloc;
        __syncthreads();
        for (int o = 128; o; o >>= 1) {
            if (t < o) {
                float m1 = sred[t], s1 = sred[256 + t];
                float m2 = sred[t + o], s2 = sred[256 + t + o];
                float M = fmaxf(m1, m2);
                float S = (s1 > 0.f ? s1 * __expf(m1 - M) : 0.f) +
                          (s2 > 0.f ? s2 * __expf(m2 - M) : 0.f);
                sred[t] = M; sred[256 + t] = S;
            }
            __syncthreads();
        }
        if (t == 0) { g_pm[b] = sred[0]; g_ps[b] = sred[256]; }
    }
    bar_arrive_wait(3);

    // ================= Final: redundant reduce + logp write =================
    {
        float m = -INFINITY, s = 0.f;
        for (int i = t; i < GRID; i += 256) {
            float mb = g_pm[i], sb = g_ps[i];
            if (mb > m) { s = s * __expf(m - mb) + sb; m = mb; }
            else        { s += sb * __expf(mb - m); }
        }
        sred[t] = m; sred[256 + t] = s;
        __syncthreads();
        for (int o = 128; o; o >>= 1) {
            if (t < o) {
                float m1 = sred[t], s1 = sred[256 + t];
                float m2 = sred[t + o], s2 = sred[256 + t + o];
                float M = fmaxf(m1, m2);
                float S = (s1 > 0.f ? s1 * __expf(m1 - M) : 0.f) +
                          (s2 > 0.f ? s2 * __expf(m2 - M) : 0.f);
                sred[t] = M; sred[256 + t] = S;
            }
            __syncthreads();
        }
        float C = sred[0] + logf(sred[256]);
        int i = b * 256 + t;
        if (i < NOUT) logp[i] = g_logits[i] - C;
    }
}

extern "C" void kernel_launch(void* const* d_in, const int* in_sizes, int n_in,
                              void* d_out, int out_size) {
    const int*   inp      = (const int*)  d_in[0];
    const float* hidden   = (const float*)d_in[1];
    const float* enc_outs = (const float*)d_in[3];
    const float* emb_W    = (const float*)d_in[4];
    const float* attn_W   = (const float*)d_in[5];
    const float* attn_b   = (const float*)d_in[6];
    const float* comb_W   = (const float*)d_in[7];
    const float* comb_b   = (const float*)d_in[8];
    const float* W_ih     = (const float*)d_in[9];
    const float* W_hh     = (const float*)d_in[10];
    const float* b_ih     = (const float*)d_in[11];
    const float* b_hh     = (const float*)d_in[12];
    const float* out_W    = (const float*)d_in[13];
    const float* out_b    = (const float*)d_in[14];

    float* out   = (float*)d_out;
    float* logp  = out;                 // [50257]
    float* hout  = out + NOUT;          // [1024]
    float* attnw = out + NOUT + NHID;   // [24]

    mega<<<GRID, 256>>>(inp, hidden, enc_outs, emb_W, attn_W, attn_b,
                        comb_W, comb_b, W_ih, W_hh, b_ih, b_hh,
                        out_W, out_b, logp, hout, attnw);
}